// round 1
// baseline (speedup 1.0000x reference)
#include <cuda_runtime.h>
#include <cuda_fp16.h>
#include <mma.h>
#include <cstdint>

using namespace nvcuda;

// ---------------------------------------------------------------------------
// Problem constants
// ---------------------------------------------------------------------------
#define BATCH   1024
#define NNEG    128
#define NLAB    100
#define ED      600
#define VFS_D   12288
#define OBJ_VD  4096

// ---------------------------------------------------------------------------
// Scratch (device globals; no allocation allowed)
// ---------------------------------------------------------------------------
__device__ __half g_Rv [BATCH * VFS_D];          // relu(vfs) fp16
__device__ __half g_X12[2048 * 4096];            // stacked sbj/obj input
__device__ __half g_Wh1[2048 * 4096];
__device__ __half g_We1[600  * 2048];
__device__ __half g_Wh2[4096 * 12288];
__device__ __half g_We2[600  * 4096];
__device__ __half g_Wh [1800 * 1800];
__device__ __half g_We [600  * 1800];
__device__ __half g_H1 [2048 * 2048];
__device__ __half g_H2 [1024 * 4096];
__device__ __half g_Z  [1024 * 1800];
__device__ __half g_H  [1024 * 1800];
__device__ float  g_emb[1024 * 600];

// ---------------------------------------------------------------------------
// fp32 -> fp16 convert (optionally with relu). n must be divisible by 4.
// ---------------------------------------------------------------------------
__global__ void cvt_f32_h16(const float* __restrict__ src, __half* __restrict__ dst,
                            int n, int do_relu) {
    int i = (blockIdx.x * blockDim.x + threadIdx.x) * 4;
    if (i >= n) return;
    float4 v = *reinterpret_cast<const float4*>(src + i);
    if (do_relu) {
        v.x = fmaxf(v.x, 0.f); v.y = fmaxf(v.y, 0.f);
        v.z = fmaxf(v.z, 0.f); v.w = fmaxf(v.w, 0.f);
    }
    __half2 h0 = __floats2half2_rn(v.x, v.y);
    __half2 h1 = __floats2half2_rn(v.z, v.w);
    *reinterpret_cast<__half2*>(dst + i)     = h0;
    *reinterpret_cast<__half2*>(dst + i + 2) = h1;
}

// ---------------------------------------------------------------------------
// Pack X12[2048,4096]: rows 0..1023 = Rv[:, 0:4096], rows 1024..2047 = Rv[:, 8192:12288]
// ---------------------------------------------------------------------------
__global__ void pack_x12() {
    const int vecs = 2048 * 4096 / 8;
    int i = blockIdx.x * blockDim.x + threadIdx.x;
    if (i >= vecs) return;
    int e = i * 8;
    int m = e >> 12;          // /4096
    int k = e & 4095;
    int src = (m & 1023) * VFS_D + ((m < 1024) ? 0 : (VFS_D - OBJ_VD)) + k;
    *reinterpret_cast<uint4*>(g_X12 + e) =
        *reinterpret_cast<const uint4*>(g_Rv + src);
}

// ---------------------------------------------------------------------------
// WMMA GEMM:  out[m,n] = act( A[m,:] . W[n,:] + bias[n] )
//   A: [M,K] fp16, row stride lda.  W: [N,K] fp16, row stride K.
//   BM=128 BN=128 BK=32, 8 warps (2x4), warp tile 64x32, frag 16x16x16 f32 acc.
//   Output: fp16 (with optional row split into out1/out2) or fp32 (outF).
// ---------------------------------------------------------------------------
#define BM 128
#define BN 128
#define BK 32
#define SPAD 8

__global__ __launch_bounds__(256)
void gemm_wmma(const __half* __restrict__ A, int lda,
               const __half* __restrict__ W,
               const float* __restrict__ bias,
               int M, int N, int K,
               __half* out1, __half* out2, float* outF,
               int ldc, int split, int do_relu) {
    __shared__ __half As[BM][BK + SPAD];
    __shared__ __half Bs[BN][BK + SPAD];
    __shared__ float  Stage[8][256];

    const int tid  = threadIdx.x;
    const int warp = tid >> 5;
    const int lane = tid & 31;
    const int wm   = warp >> 2;   // 0..1
    const int wn   = warp & 3;    // 0..3
    const int m0   = blockIdx.y * BM;
    const int n0   = blockIdx.x * BN;

    wmma::fragment<wmma::accumulator, 16, 16, 16, float> acc[4][2];
#pragma unroll
    for (int i = 0; i < 4; i++)
#pragma unroll
        for (int j = 0; j < 2; j++)
            wmma::fill_fragment(acc[i][j], 0.0f);

    for (int k0 = 0; k0 < K; k0 += BK) {
        // ---- load A tile (4096 halves = 512 x vec8; 2 per thread) ----
#pragma unroll
        for (int t = 0; t < 2; t++) {
            int v  = tid * 2 + t;
            int r  = v >> 2;
            int c8 = (v & 3) * 8;
            int gk = k0 + c8;
            __half* dst = &As[r][c8];
            const __half* srcp = A + (size_t)(m0 + r) * lda + gk;
            if (gk + 8 <= K) {
                *reinterpret_cast<uint4*>(dst) = *reinterpret_cast<const uint4*>(srcp);
            } else {
#pragma unroll
                for (int e = 0; e < 8; e++)
                    dst[e] = (gk + e < K) ? srcp[e] : __half(0.f);
            }
        }
        // ---- load W tile ----
#pragma unroll
        for (int t = 0; t < 2; t++) {
            int v  = tid * 2 + t;
            int r  = v >> 2;
            int c8 = (v & 3) * 8;
            int gn = n0 + r;
            int gk = k0 + c8;
            __half* dst = &Bs[r][c8];
            if (gn < N && gk + 8 <= K) {
                *reinterpret_cast<uint4*>(dst) =
                    *reinterpret_cast<const uint4*>(W + (size_t)gn * K + gk);
            } else if (gn < N) {
#pragma unroll
                for (int e = 0; e < 8; e++)
                    dst[e] = (gk + e < K) ? W[(size_t)gn * K + gk + e] : __half(0.f);
            } else {
#pragma unroll
                for (int e = 0; e < 8; e++) dst[e] = __half(0.f);
            }
        }
        __syncthreads();

#pragma unroll
        for (int kk = 0; kk < BK; kk += 16) {
            wmma::fragment<wmma::matrix_a, 16, 16, 16, __half, wmma::row_major> af[4];
            wmma::fragment<wmma::matrix_b, 16, 16, 16, __half, wmma::col_major> bf[2];
#pragma unroll
            for (int i = 0; i < 4; i++)
                wmma::load_matrix_sync(af[i], &As[wm * 64 + i * 16][kk], BK + SPAD);
#pragma unroll
            for (int j = 0; j < 2; j++)
                wmma::load_matrix_sync(bf[j], &Bs[wn * 32 + j * 16][kk], BK + SPAD);
#pragma unroll
            for (int i = 0; i < 4; i++)
#pragma unroll
                for (int j = 0; j < 2; j++)
                    wmma::mma_sync(acc[i][j], af[i], bf[j], acc[i][j]);
        }
        __syncthreads();
    }

    // ---- epilogue: stage each 16x16 frag through smem, apply bias/relu ----
    float* st = &Stage[warp][0];
#pragma unroll
    for (int i = 0; i < 4; i++) {
#pragma unroll
        for (int j = 0; j < 2; j++) {
            wmma::store_matrix_sync(st, acc[i][j], 16, wmma::mem_row_major);
            __syncwarp();
            int m_base = m0 + wm * 64 + i * 16;
            int n_base = n0 + wn * 32 + j * 16;
#pragma unroll
            for (int e = 0; e < 8; e++) {
                int idx = lane * 8 + e;
                int r = idx >> 4, c = idx & 15;
                int gm = m_base + r;
                int gn = n_base + c;
                if (gn < N) {
                    float vv = st[idx] + bias[gn];
                    if (do_relu) vv = fmaxf(vv, 0.f);
                    if (outF) {
                        outF[(size_t)gm * ldc + gn] = vv;
                    } else {
                        __half hv = __float2half(vv);
                        if (gm < split) out1[(size_t)gm * ldc + gn] = hv;
                        else            out2[(size_t)(gm - split) * ldc + gn] = hv;
                    }
                }
            }
            __syncwarp();
        }
    }
}

// ---------------------------------------------------------------------------
// Scoring: out[b,0] = po(L[pls[b]], emb[b]); out[b,1+j] = po(L[nls[b,j]], emb[b])
//   po(a,e) = -sqrt(sum relu(a - e)^2)
// ---------------------------------------------------------------------------
__global__ void score_kernel(const float* __restrict__ L,
                             const int* __restrict__ pls,
                             const int* __restrict__ nls,
                             float* __restrict__ out) {
    int b = blockIdx.x;
    __shared__ float es[ED];
    for (int i = threadIdx.x; i < ED; i += blockDim.x) es[i] = g_emb[b * ED + i];
    __syncthreads();

    int warp = threadIdx.x >> 5;
    int lane = threadIdx.x & 31;
    for (int j = warp; j < NNEG + 1; j += 8) {
        int idx = (j == 0) ? pls[b] : nls[b * NNEG + (j - 1)];
        const float* Lr = L + (size_t)idx * ED;
        float s = 0.f;
        for (int c = lane; c < ED; c += 32) {
            float d = Lr[c] - es[c];
            d = fmaxf(d, 0.f);
            s += d * d;
        }
#pragma unroll
        for (int o = 16; o; o >>= 1) s += __shfl_xor_sync(0xffffffffu, s, o);
        if (lane == 0) out[b * (NNEG + 1) + j] = -sqrtf(s);
    }
}

// ---------------------------------------------------------------------------
// Launch
// ---------------------------------------------------------------------------
static inline int cdiv(int a, int b) { return (a + b - 1) / b; }

extern "C" void kernel_launch(void* const* d_in, const int* in_sizes, int n_in,
                              void* d_out, int out_size) {
    const float* vfs  = (const float*)d_in[0];
    const float* L    = (const float*)d_in[1];
    const int*   pls  = (const int*)  d_in[2];
    const int*   nls  = (const int*)  d_in[3];
    const float* W_h1 = (const float*)d_in[4];
    const float* b_h1 = (const float*)d_in[5];
    const float* W_e1 = (const float*)d_in[6];
    const float* b_e1 = (const float*)d_in[7];
    const float* W_h2 = (const float*)d_in[8];
    const float* b_h2 = (const float*)d_in[9];
    const float* W_e2 = (const float*)d_in[10];
    const float* b_e2 = (const float*)d_in[11];
    const float* W_h  = (const float*)d_in[12];
    const float* b_h  = (const float*)d_in[13];
    const float* W_e  = (const float*)d_in[14];
    const float* b_e  = (const float*)d_in[15];
    float* out = (float*)d_out;

    __half *pRv, *pX12, *pWh1, *pWe1, *pWh2, *pWe2, *pWh, *pWe;
    __half *pH1, *pH2, *pZ, *pH;
    float  *pEmb;
    cudaGetSymbolAddress((void**)&pRv,  g_Rv);
    cudaGetSymbolAddress((void**)&pX12, g_X12);
    cudaGetSymbolAddress((void**)&pWh1, g_Wh1);
    cudaGetSymbolAddress((void**)&pWe1, g_We1);
    cudaGetSymbolAddress((void**)&pWh2, g_Wh2);
    cudaGetSymbolAddress((void**)&pWe2, g_We2);
    cudaGetSymbolAddress((void**)&pWh,  g_Wh);
    cudaGetSymbolAddress((void**)&pWe,  g_We);
    cudaGetSymbolAddress((void**)&pH1,  g_H1);
    cudaGetSymbolAddress((void**)&pH2,  g_H2);
    cudaGetSymbolAddress((void**)&pZ,   g_Z);
    cudaGetSymbolAddress((void**)&pH,   g_H);
    cudaGetSymbolAddress((void**)&pEmb, g_emb);

    const int T = 256;
    auto cvt = [&](const float* s, __half* d, int n, int relu_) {
        cvt_f32_h16<<<cdiv(n / 4, T), T>>>(s, d, n, relu_);
    };

    // 1) relu(vfs) -> fp16, weights -> fp16
    cvt(vfs,  pRv,  BATCH * VFS_D, 1);
    cvt(W_h1, pWh1, 2048 * 4096, 0);
    cvt(W_e1, pWe1, 600  * 2048, 0);
    cvt(W_h2, pWh2, 4096 * 12288, 0);
    cvt(W_e2, pWe2, 600  * 4096, 0);
    cvt(W_h,  pWh,  1800 * 1800, 0);
    cvt(W_e,  pWe,  600  * 1800, 0);

    // 2) stack sbj/obj inputs
    pack_x12<<<cdiv(2048 * 4096 / 8, T), T>>>();

    dim3 blk(256);
    // 3) GEMM A: H1 = relu(X12 @ Wh1^T + b_h1)    [2048 x 2048]
    gemm_wmma<<<dim3(2048 / BN, 2048 / BM), blk>>>(
        pX12, 4096, pWh1, b_h1, 2048, 2048, 4096,
        pH1, pH1, nullptr, 2048, 2048, 1);
    // 4) GEMM C: H2 = relu(Rv @ Wh2^T + b_h2)     [1024 x 4096]
    gemm_wmma<<<dim3(4096 / BN, 1024 / BM), blk>>>(
        pRv, VFS_D, pWh2, b_h2, 1024, 4096, VFS_D,
        pH2, pH2, nullptr, 4096, 1024, 1);
    // 5) GEMM B: E1 = relu(H1 @ We1^T + b_e1) -> Z[:,0:600] (sbj) / Z[:,1200:1800] (obj)
    gemm_wmma<<<dim3(cdiv(600, BN), 2048 / BM), blk>>>(
        pH1, 2048, pWe1, b_e1, 2048, 600, 2048,
        pZ, pZ + 1200, nullptr, 1800, 1024, 1);
    // 6) GEMM D: E2 = relu(H2 @ We2^T + b_e2) -> Z[:,600:1200]
    gemm_wmma<<<dim3(cdiv(600, BN), 1024 / BM), blk>>>(
        pH2, 4096, pWe2, b_e2, 1024, 600, 4096,
        pZ + 600, pZ + 600, nullptr, 1800, 1024, 1);
    // 7) GEMM E: H = relu(Z @ Wh^T + b_h)          [1024 x 1800]
    gemm_wmma<<<dim3(cdiv(1800, BN), 1024 / BM), blk>>>(
        pZ, 1800, pWh, b_h, 1024, 1800, 1800,
        pH, pH, nullptr, 1800, 1024, 1);
    // 8) GEMM F: emb = H @ We^T + b_e (no relu)    [1024 x 600] fp32
    gemm_wmma<<<dim3(cdiv(600, BN), 1024 / BM), blk>>>(
        pH, 1800, pWe, b_e, 1024, 600, 1800,
        nullptr, nullptr, pEmb, 600, 1024, 0);

    // 9) scoring
    score_kernel<<<BATCH, 256>>>(L, pls, nls, out);
}

// round 2
// speedup vs baseline: 1.7778x; 1.7778x over previous
#include <cuda_runtime.h>
#include <cuda_fp16.h>
#include <mma.h>
#include <cstdint>

using namespace nvcuda;

// ---------------------------------------------------------------------------
// Problem constants
// ---------------------------------------------------------------------------
#define BATCH   1024
#define NNEG    128
#define ED      600
#define VFS_D   12288
#define OBJ_VD  4096

// Padded dims
#define KP18    1856            // 1800 padded to multiple of 64
#define NP600   640             // 600 padded to multiple of 128
#define NP1800  1920            // 1800 padded to multiple of 128

// ---------------------------------------------------------------------------
// Scratch (device globals; no allocation allowed)
// ---------------------------------------------------------------------------
__device__ __half g_Rv [BATCH * VFS_D];
__device__ __half g_X12[2048 * 4096];
__device__ __half g_Wh1[2048 * 4096];
__device__ __half g_We1[NP600 * 2048];
__device__ __half g_Wh2[4096 * 12288];
__device__ __half g_We2[NP600 * 4096];
__device__ __half g_Wh [NP1800 * KP18];
__device__ __half g_We [NP600 * KP18];
__device__ __half g_H1 [2048 * 2048];
__device__ __half g_H2 [1024 * 4096];
__device__ __half g_Z  [1024 * KP18];
__device__ __half g_H  [1024 * KP18];
__device__ float  g_emb[1024 * ED];

// ---------------------------------------------------------------------------
// cp.async helpers
// ---------------------------------------------------------------------------
__device__ __forceinline__ uint32_t sptr(const void* p) {
    return (uint32_t)__cvta_generic_to_shared(p);
}
__device__ __forceinline__ void cp16(uint32_t s, const void* g) {
    asm volatile("cp.async.cg.shared.global [%0], [%1], 16;" :: "r"(s), "l"(g));
}
__device__ __forceinline__ void cp_commit() {
    asm volatile("cp.async.commit_group;");
}
template<int N> __device__ __forceinline__ void cp_wait() {
    asm volatile("cp.async.wait_group %0;" :: "n"(N));
}

// ---------------------------------------------------------------------------
// fp32 -> fp16 converts
// ---------------------------------------------------------------------------
__global__ void cvt_f32_h16(const float* __restrict__ src, __half* __restrict__ dst,
                            int n, int do_relu) {
    int i = (blockIdx.x * blockDim.x + threadIdx.x) * 4;
    if (i >= n) return;
    float4 v = *reinterpret_cast<const float4*>(src + i);
    if (do_relu) {
        v.x = fmaxf(v.x, 0.f); v.y = fmaxf(v.y, 0.f);
        v.z = fmaxf(v.z, 0.f); v.w = fmaxf(v.w, 0.f);
    }
    *reinterpret_cast<__half2*>(dst + i)     = __floats2half2_rn(v.x, v.y);
    *reinterpret_cast<__half2*>(dst + i + 2) = __floats2half2_rn(v.z, v.w);
}

// strided convert: R rows of Ks floats (Ks%4==0) -> dst rows of stride Kd halves
__global__ void cvt2d_f32_h16(const float* __restrict__ src, __half* __restrict__ dst,
                              int R, int Ks, int Kd) {
    int i = (blockIdx.x * blockDim.x + threadIdx.x) * 4;
    if (i >= R * Ks) return;
    int r = i / Ks, c = i - r * Ks;
    float4 v = *reinterpret_cast<const float4*>(src + i);
    __half* d = dst + (size_t)r * Kd + c;
    *reinterpret_cast<__half2*>(d)     = __floats2half2_rn(v.x, v.y);
    *reinterpret_cast<__half2*>(d + 2) = __floats2half2_rn(v.z, v.w);
}

// ---------------------------------------------------------------------------
// Pack X12[2048,4096]
// ---------------------------------------------------------------------------
__global__ void pack_x12() {
    const int vecs = 2048 * 4096 / 8;
    int i = blockIdx.x * blockDim.x + threadIdx.x;
    if (i >= vecs) return;
    int e = i * 8;
    int m = e >> 12;
    int k = e & 4095;
    int src = (m & 1023) * VFS_D + ((m < 1024) ? 0 : (VFS_D - OBJ_VD)) + k;
    *reinterpret_cast<uint4*>(g_X12 + e) = *reinterpret_cast<const uint4*>(g_Rv + src);
}

// ---------------------------------------------------------------------------
// Double-buffered cp.async WMMA GEMM.
//   BM=BN=128, BK=64, 8 warps (2x4), warp tile 64x32.
//   All loads unpredicated: M % 128 == 0, N (weight rows) padded to 128,
//   K padded to 64. Store guard gn < N only.
// ---------------------------------------------------------------------------
#define LDS 72   // halves per smem row (64 + 8 pad)

__global__ __launch_bounds__(256)
void gemm_wmma2(const __half* __restrict__ A, int lda,
                const __half* __restrict__ W, int ldw,
                const float* __restrict__ bias,
                int N, int K,
                __half* out1, __half* out2, float* outF,
                int ldc, int split, int do_relu) {
    extern __shared__ __half sm[];
    __half* Asm = sm;                    // [2][128][LDS]
    __half* Bsm = sm + 2 * 128 * LDS;    // [2][128][LDS]

    const int tid  = threadIdx.x;
    const int warp = tid >> 5;
    const int lane = tid & 31;
    const int wm   = warp >> 2;   // 0..1
    const int wn   = warp & 3;    // 0..3
    const int m0   = blockIdx.y * 128;
    const int n0   = blockIdx.x * 128;

    wmma::fragment<wmma::accumulator, 16, 16, 16, float> acc[4][2];
#pragma unroll
    for (int i = 0; i < 4; i++)
#pragma unroll
        for (int j = 0; j < 2; j++)
            wmma::fill_fragment(acc[i][j], 0.0f);

    const int KT = K >> 6;

    // async load of K-tile kt into buffer kt&1
    auto issue = [&](int kt) {
        const int k0 = kt << 6;
        __half* a = Asm + (kt & 1) * 128 * LDS;
        __half* b = Bsm + (kt & 1) * 128 * LDS;
#pragma unroll
        for (int t = 0; t < 4; t++) {
            int v = tid + t * 256;
            int r = v >> 3;
            int c = (v & 7) << 3;
            cp16(sptr(a + r * LDS + c), A + (size_t)(m0 + r) * lda + k0 + c);
            cp16(sptr(b + r * LDS + c), W + (size_t)(n0 + r) * ldw + k0 + c);
        }
        cp_commit();
    };

    issue(0);
    for (int kt = 0; kt < KT; kt++) {
        if (kt + 1 < KT) { issue(kt + 1); cp_wait<1>(); }
        else             { cp_wait<0>(); }
        __syncthreads();

        const __half* a = Asm + (kt & 1) * 128 * LDS;
        const __half* b = Bsm + (kt & 1) * 128 * LDS;
#pragma unroll
        for (int kk = 0; kk < 64; kk += 16) {
            wmma::fragment<wmma::matrix_a, 16, 16, 16, __half, wmma::row_major> af[4];
            wmma::fragment<wmma::matrix_b, 16, 16, 16, __half, wmma::col_major> bf[2];
#pragma unroll
            for (int i = 0; i < 4; i++)
                wmma::load_matrix_sync(af[i], a + (wm * 64 + i * 16) * LDS + kk, LDS);
#pragma unroll
            for (int j = 0; j < 2; j++)
                wmma::load_matrix_sync(bf[j], b + (wn * 32 + j * 16) * LDS + kk, LDS);
#pragma unroll
            for (int i = 0; i < 4; i++)
#pragma unroll
                for (int j = 0; j < 2; j++)
                    wmma::mma_sync(acc[i][j], af[i], bf[j], acc[i][j]);
        }
        __syncthreads();
    }

    // ---- epilogue: stage frags through (reused) smem, bias + relu + store ----
    float* st = reinterpret_cast<float*>(sm) + warp * 256;
#pragma unroll
    for (int i = 0; i < 4; i++) {
#pragma unroll
        for (int j = 0; j < 2; j++) {
            wmma::store_matrix_sync(st, acc[i][j], 16, wmma::mem_row_major);
            __syncwarp();
            int m_base = m0 + wm * 64 + i * 16;
            int n_base = n0 + wn * 32 + j * 16;
#pragma unroll
            for (int e = 0; e < 8; e++) {
                int idx = lane * 8 + e;
                int r = idx >> 4, c = idx & 15;
                int gm = m_base + r;
                int gn = n_base + c;
                if (gn < N) {
                    float vv = st[idx] + bias[gn];
                    if (do_relu) vv = fmaxf(vv, 0.f);
                    if (outF) {
                        outF[(size_t)gm * ldc + gn] = vv;
                    } else {
                        __half hv = __float2half(vv);
                        if (gm < split) out1[(size_t)gm * ldc + gn] = hv;
                        else            out2[(size_t)(gm - split) * ldc + gn] = hv;
                    }
                }
            }
            __syncwarp();
        }
    }
}

// ---------------------------------------------------------------------------
// Scoring
// ---------------------------------------------------------------------------
__global__ void score_kernel(const float* __restrict__ L,
                             const int* __restrict__ pls,
                             const int* __restrict__ nls,
                             float* __restrict__ out) {
    int b = blockIdx.x;
    __shared__ float es[ED];
    for (int i = threadIdx.x; i < ED; i += blockDim.x) es[i] = g_emb[b * ED + i];
    __syncthreads();

    int warp = threadIdx.x >> 5;
    int lane = threadIdx.x & 31;
    for (int j = warp; j < NNEG + 1; j += 8) {
        int idx = (j == 0) ? pls[b] : nls[b * NNEG + (j - 1)];
        const float* Lr = L + (size_t)idx * ED;
        float s = 0.f;
        for (int c = lane; c < ED; c += 32) {
            float d = fmaxf(Lr[c] - es[c], 0.f);
            s += d * d;
        }
#pragma unroll
        for (int o = 16; o; o >>= 1) s += __shfl_xor_sync(0xffffffffu, s, o);
        if (lane == 0) out[b * (NNEG + 1) + j] = -sqrtf(s);
    }
}

// ---------------------------------------------------------------------------
// Launch
// ---------------------------------------------------------------------------
static inline int cdiv(int a, int b) { return (a + b - 1) / b; }

extern "C" void kernel_launch(void* const* d_in, const int* in_sizes, int n_in,
                              void* d_out, int out_size) {
    const float* vfs  = (const float*)d_in[0];
    const float* L    = (const float*)d_in[1];
    const int*   pls  = (const int*)  d_in[2];
    const int*   nls  = (const int*)  d_in[3];
    const float* W_h1 = (const float*)d_in[4];
    const float* b_h1 = (const float*)d_in[5];
    const float* W_e1 = (const float*)d_in[6];
    const float* b_e1 = (const float*)d_in[7];
    const float* W_h2 = (const float*)d_in[8];
    const float* b_h2 = (const float*)d_in[9];
    const float* W_e2 = (const float*)d_in[10];
    const float* b_e2 = (const float*)d_in[11];
    const float* W_h  = (const float*)d_in[12];
    const float* b_h  = (const float*)d_in[13];
    const float* W_e  = (const float*)d_in[14];
    const float* b_e  = (const float*)d_in[15];
    float* out = (float*)d_out;

    __half *pRv, *pX12, *pWh1, *pWe1, *pWh2, *pWe2, *pWh, *pWe;
    __half *pH1, *pH2, *pZ, *pH;
    float  *pEmb;
    cudaGetSymbolAddress((void**)&pRv,  g_Rv);
    cudaGetSymbolAddress((void**)&pX12, g_X12);
    cudaGetSymbolAddress((void**)&pWh1, g_Wh1);
    cudaGetSymbolAddress((void**)&pWe1, g_We1);
    cudaGetSymbolAddress((void**)&pWh2, g_Wh2);
    cudaGetSymbolAddress((void**)&pWe2, g_We2);
    cudaGetSymbolAddress((void**)&pWh,  g_Wh);
    cudaGetSymbolAddress((void**)&pWe,  g_We);
    cudaGetSymbolAddress((void**)&pH1,  g_H1);
    cudaGetSymbolAddress((void**)&pH2,  g_H2);
    cudaGetSymbolAddress((void**)&pZ,   g_Z);
    cudaGetSymbolAddress((void**)&pH,   g_H);
    cudaGetSymbolAddress((void**)&pEmb, g_emb);

    const int SMEM_BYTES = 4 * 128 * LDS * 2;  // 73728
    cudaFuncSetAttribute(gemm_wmma2, cudaFuncAttributeMaxDynamicSharedMemorySize, SMEM_BYTES);

    const int T = 256;

    // ---- zero the padded regions (pads never written by cvt/GEMM) ----
    cudaMemsetAsync(pWe1 + 600 * 2048, 0, (size_t)(NP600 - 600) * 2048 * 2);
    cudaMemsetAsync(pWe2 + 600 * 4096, 0, (size_t)(NP600 - 600) * 4096 * 2);
    cudaMemsetAsync(pWh,  0, (size_t)NP1800 * KP18 * 2);
    cudaMemsetAsync(pWe,  0, (size_t)NP600 * KP18 * 2);
    cudaMemsetAsync(pZ,   0, (size_t)1024 * KP18 * 2);
    cudaMemsetAsync(pH,   0, (size_t)1024 * KP18 * 2);

    // ---- converts ----
    auto cvt = [&](const float* s, __half* d, int n, int relu_) {
        cvt_f32_h16<<<cdiv(n / 4, T), T>>>(s, d, n, relu_);
    };
    cvt(vfs,  pRv,  BATCH * VFS_D, 1);
    cvt(W_h1, pWh1, 2048 * 4096, 0);
    cvt(W_e1, pWe1, 600  * 2048, 0);
    cvt(W_h2, pWh2, 4096 * 12288, 0);
    cvt(W_e2, pWe2, 600  * 4096, 0);
    cvt2d_f32_h16<<<cdiv(1800 * 1800 / 4, T), T>>>(W_h, pWh, 1800, 1800, KP18);
    cvt2d_f32_h16<<<cdiv(600  * 1800 / 4, T), T>>>(W_e, pWe, 600,  1800, KP18);

    pack_x12<<<cdiv(2048 * 4096 / 8, T), T>>>();

    dim3 blk(256);
    // GEMM A: H1 = relu(X12 @ Wh1^T + b_h1)   [2048 x 2048], K=4096
    gemm_wmma2<<<dim3(16, 16), blk, SMEM_BYTES>>>(
        pX12, 4096, pWh1, 4096, b_h1, 2048, 4096,
        pH1, pH1, nullptr, 2048, 2048, 1);
    // GEMM C: H2 = relu(Rv @ Wh2^T + b_h2)    [1024 x 4096], K=12288
    gemm_wmma2<<<dim3(32, 8), blk, SMEM_BYTES>>>(
        pRv, VFS_D, pWh2, VFS_D, b_h2, 4096, VFS_D,
        pH2, pH2, nullptr, 4096, 1024, 1);
    // GEMM B: E1 -> Z[:,0:600] (sbj rows<1024) / Z[:,1200:1800] (obj)
    gemm_wmma2<<<dim3(5, 16), blk, SMEM_BYTES>>>(
        pH1, 2048, pWe1, 2048, b_e1, 600, 2048,
        pZ, pZ + 1200, nullptr, KP18, 1024, 1);
    // GEMM D: E2 -> Z[:,600:1200]
    gemm_wmma2<<<dim3(5, 8), blk, SMEM_BYTES>>>(
        pH2, 4096, pWe2, 4096, b_e2, 600, 4096,
        pZ + 600, pZ + 600, nullptr, KP18, 1024, 1);
    // GEMM E: H = relu(Z @ Wh^T + b_h)        [1024 x 1800], K=1856 (padded)
    gemm_wmma2<<<dim3(15, 8), blk, SMEM_BYTES>>>(
        pZ, KP18, pWh, KP18, b_h, 1800, KP18,
        pH, pH, nullptr, KP18, 1024, 1);
    // GEMM F: emb = H @ We^T + b_e            [1024 x 600] fp32
    gemm_wmma2<<<dim3(5, 8), blk, SMEM_BYTES>>>(
        pH, KP18, pWe, KP18, b_e, 600, KP18,
        nullptr, nullptr, pEmb, ED, 1024, 0);

    score_kernel<<<BATCH, 256>>>(L, pls, nls, out);
}

// round 4
// speedup vs baseline: 3.2747x; 1.8420x over previous
#include <cuda_runtime.h>
#include <cuda_bf16.h>
#include <mma.h>
#include <cstdint>

using namespace nvcuda;

// Detect whether this compilation pass supports arch-specific (tcgen05) features.
#if defined(__CUDA_ARCH_SPECIFIC__) || defined(__CUDA_ARCH_FEAT_SM103_ALL) || defined(__CUDA_ARCH_FEAT_SM100_ALL)
#define HAS_TCGEN05 1
#else
#define HAS_TCGEN05 0
#endif

// ---------------------------------------------------------------------------
// Problem constants
// ---------------------------------------------------------------------------
#define BATCH   1024
#define NNEG    128
#define ED      600
#define VFS_D   12288
#define OBJ_VD  4096

#define KP18    1920            // 1800 padded to multiple of 128
#define NP600   640             // 600 padded to multiple of 128
#define NP1800  1920

// ---------------------------------------------------------------------------
// Scratch (device globals)
// ---------------------------------------------------------------------------
__device__ __nv_bfloat16 g_Rv [BATCH * VFS_D];
__device__ __nv_bfloat16 g_X12[2048 * 4096];
__device__ __nv_bfloat16 g_Wh1[2048 * 4096];
__device__ __nv_bfloat16 g_We1[NP600 * 2048];
__device__ __nv_bfloat16 g_Wh2[4096 * 12288];
__device__ __nv_bfloat16 g_We2[NP600 * 4096];
__device__ __nv_bfloat16 g_Wh [NP1800 * KP18];
__device__ __nv_bfloat16 g_We [NP600 * KP18];
__device__ __nv_bfloat16 g_H1 [2048 * 2048];
__device__ __nv_bfloat16 g_H2 [1024 * 4096];
__device__ __nv_bfloat16 g_Z  [1024 * KP18];
__device__ __nv_bfloat16 g_H  [1024 * KP18];
__device__ float         g_emb[1024 * ED];

// ---------------------------------------------------------------------------
// PTX helpers (safe on all targets)
// ---------------------------------------------------------------------------
__device__ __forceinline__ uint32_t sptr(const void* p) {
    return (uint32_t)__cvta_generic_to_shared(p);
}
__device__ __forceinline__ void cp16(uint32_t s, const void* g) {
    asm volatile("cp.async.cg.shared.global [%0], [%1], 16;" :: "r"(s), "l"(g));
}
__device__ __forceinline__ void cp_commit() {
    asm volatile("cp.async.commit_group;");
}
template<int N> __device__ __forceinline__ void cp_wait() {
    asm volatile("cp.async.wait_group %0;" :: "n"(N));
}

#if HAS_TCGEN05
__device__ __forceinline__ uint32_t elect1() {
    uint32_t r;
    asm volatile("{\n\t.reg .pred p;\n\telect.sync _|p, 0xFFFFFFFF;\n\t"
                 "selp.b32 %0, 1, 0, p;\n\t}" : "=r"(r));
    return r;
}

#define TCGEN05_ALLOC(saddr, ncols) \
    asm volatile("tcgen05.alloc.cta_group::1.sync.aligned.shared::cta.b32 [%0], %1;" \
                 :: "r"((uint32_t)(saddr)), "r"((uint32_t)(ncols)) : "memory")
#define TCGEN05_DEALLOC(tmem, ncols) \
    asm volatile("tcgen05.dealloc.cta_group::1.sync.aligned.b32 %0, %1;" \
                 :: "r"(tmem), "r"((uint32_t)(ncols)))
#define TCGEN05_RELINQUISH() \
    asm volatile("tcgen05.relinquish_alloc_permit.cta_group::1.sync.aligned;")
#define TCGEN05_COMMIT(mbar) \
    asm volatile("tcgen05.commit.cta_group::1.mbarrier::arrive::one.shared::cluster.b64 [%0];" \
                 :: "r"((uint32_t)(mbar)) : "memory")
#define TCGEN05_FENCE_AFTER() \
    asm volatile("tcgen05.fence::after_thread_sync;" ::: "memory")
#define TCGEN05_FENCE_BEFORE() \
    asm volatile("tcgen05.fence::before_thread_sync;" ::: "memory")
#define TCGEN05_WAIT_LD() \
    asm volatile("tcgen05.wait::ld.sync.aligned;" ::: "memory")
#define FENCE_PROXY_ASYNC() \
    asm volatile("fence.proxy.async.shared::cta;" ::: "memory")
#define MBARRIER_INIT(mbar, cnt) \
    asm volatile("mbarrier.init.shared.b64 [%0], %1;" \
                 :: "r"((uint32_t)(mbar)), "r"((uint32_t)(cnt)) : "memory")

#define MBARRIER_WAIT_PARITY(mbar_smem_addr, phase_parity) do { \
    uint32_t _mbar = (uint32_t)(mbar_smem_addr); \
    uint32_t _parity = (uint32_t)(phase_parity); \
    uint32_t _done; \
    asm volatile( \
        "{\n\t.reg .pred p;\n\t" \
        "mbarrier.try_wait.parity.acquire.cta.shared::cta.b64 p, [%1], %2;\n\t" \
        "selp.b32 %0, 1, 0, p;\n\t}" \
        : "=r"(_done) : "r"(_mbar), "r"(_parity) : "memory"); \
    if (!_done) { \
        asm volatile( \
            "{\n\t.reg .pred P1;\n\t" \
            "WAIT_LOOP_%=:\n\t" \
            "mbarrier.try_wait.parity.acquire.cta.shared::cta.b64 P1, [%0], %1, 0x989680;\n\t" \
            "@P1 bra.uni WAIT_DONE_%=;\n\t" \
            "bra.uni WAIT_LOOP_%=;\n\t" \
            "WAIT_DONE_%=:\n\t}" \
            :: "r"(_mbar), "r"(_parity) : "memory"); \
    } \
} while(0)

#define TCGEN05_LD_32X32B_X32(r, tmem_addr) \
    asm volatile( \
        "tcgen05.ld.sync.aligned.32x32b.x32.b32 " \
        "{%0, %1, %2, %3, %4, %5, %6, %7, " \
        " %8, %9, %10, %11, %12, %13, %14, %15, " \
        " %16, %17, %18, %19, %20, %21, %22, %23, " \
        " %24, %25, %26, %27, %28, %29, %30, %31}, [%32];" \
        : "=r"((r)[0]),  "=r"((r)[1]),  "=r"((r)[2]),  "=r"((r)[3]), \
          "=r"((r)[4]),  "=r"((r)[5]),  "=r"((r)[6]),  "=r"((r)[7]), \
          "=r"((r)[8]),  "=r"((r)[9]),  "=r"((r)[10]), "=r"((r)[11]), \
          "=r"((r)[12]), "=r"((r)[13]), "=r"((r)[14]), "=r"((r)[15]), \
          "=r"((r)[16]), "=r"((r)[17]), "=r"((r)[18]), "=r"((r)[19]), \
          "=r"((r)[20]), "=r"((r)[21]), "=r"((r)[22]), "=r"((r)[23]), \
          "=r"((r)[24]), "=r"((r)[25]), "=r"((r)[26]), "=r"((r)[27]), \
          "=r"((r)[28]), "=r"((r)[29]), "=r"((r)[30]), "=r"((r)[31]) \
        : "r"(tmem_addr))

// SW128 K-major smem descriptor: layout=2, version=1, SBO=64, LBO=1
static constexpr uint64_t DESC_BASE =
    (uint64_t(2) << 61) | (uint64_t(1) << 46) | (uint64_t(64) << 32) | (uint64_t(1) << 16);

// idesc: kind::f16, dtype=F32, atype=btype=BF16, N=128, M=128
#define IDESC 0x8200490u

__device__ __forceinline__ void mma_bf16_ss(uint32_t d, uint64_t ad, uint64_t bd,
                                            uint32_t enable) {
    asm volatile(
        "{\n\t.reg .pred p;\n\tsetp.ne.u32 p, %4, 0;\n\t"
        "tcgen05.mma.cta_group::1.kind::f16 [%0], %1, %2, %3, {%5,%5,%5,%5}, p;\n\t}"
        :: "r"(d), "l"(ad), "l"(bd), "r"(IDESC), "r"(enable), "r"(0u) : "memory");
}
#endif  // HAS_TCGEN05

// ---------------------------------------------------------------------------
// Converts / pack
// ---------------------------------------------------------------------------
static inline int cdiv(int a, int b) { return (a + b - 1) / b; }

__global__ void cvt_f32_b16(const float* __restrict__ src, __nv_bfloat16* __restrict__ dst,
                            int n, int do_relu) {
    int i = (blockIdx.x * blockDim.x + threadIdx.x) * 4;
    if (i >= n) return;
    float4 v = *reinterpret_cast<const float4*>(src + i);
    if (do_relu) {
        v.x = fmaxf(v.x, 0.f); v.y = fmaxf(v.y, 0.f);
        v.z = fmaxf(v.z, 0.f); v.w = fmaxf(v.w, 0.f);
    }
    *reinterpret_cast<__nv_bfloat162*>(dst + i)     = __floats2bfloat162_rn(v.x, v.y);
    *reinterpret_cast<__nv_bfloat162*>(dst + i + 2) = __floats2bfloat162_rn(v.z, v.w);
}

__global__ void cvt2d_f32_b16(const float* __restrict__ src, __nv_bfloat16* __restrict__ dst,
                              int R, int Ks, int Kd) {
    int i = (blockIdx.x * blockDim.x + threadIdx.x) * 4;
    if (i >= R * Ks) return;
    int r = i / Ks, c = i - r * Ks;
    float4 v = *reinterpret_cast<const float4*>(src + i);
    __nv_bfloat16* d = dst + (size_t)r * Kd + c;
    *reinterpret_cast<__nv_bfloat162*>(d)     = __floats2bfloat162_rn(v.x, v.y);
    *reinterpret_cast<__nv_bfloat162*>(d + 2) = __floats2bfloat162_rn(v.z, v.w);
}

__global__ void pack_x12() {
    const int vecs = 2048 * 4096 / 8;
    int i = blockIdx.x * blockDim.x + threadIdx.x;
    if (i >= vecs) return;
    int e = i * 8;
    int m = e >> 12;
    int k = e & 4095;
    int src = (m & 1023) * VFS_D + ((m < 1024) ? 0 : (VFS_D - OBJ_VD)) + k;
    *reinterpret_cast<uint4*>(g_X12 + e) = *reinterpret_cast<const uint4*>(g_Rv + src);
}

// ---------------------------------------------------------------------------
// GEMM: out[m,n] = act(A[m,:].W[n,:] + bias[n])
//   A: [M,K] bf16 row-major (lda), W: [N,K] bf16 row-major (ldw)
//   M%128==0, K%128==0, W rows padded to multiple of 128.
//   tcgen05 body when the compile pass supports it; wmma fallback otherwise.
// ---------------------------------------------------------------------------
#define STAGES    3
#define STG_BYTES 65536          // A 32KB + B 32KB
#define ABYTES    32768
#define GEMM_SMEM 198656

__global__ __launch_bounds__(256)
void gemm_tc(const __nv_bfloat16* __restrict__ A, int lda,
             const __nv_bfloat16* __restrict__ W, int ldw,
             const float* __restrict__ bias,
             int N, int K,
             __nv_bfloat16* out1, __nv_bfloat16* out2, float* outF,
             int ldc, int split, int do_relu) {
#if HAS_TCGEN05
    // ======================= tcgen05 path =======================
    extern __shared__ char smraw[];
    const uint32_t sm0   = sptr(smraw);
    const uint32_t sA0   = (sm0 + 2047) & ~1023u;
    const uint32_t mbar0 = sm0 + 8;
    float* biasS = reinterpret_cast<float*>(smraw + 64);

    const int tid  = threadIdx.x;
    const int warp = tid >> 5;
    const int lane = tid & 31;
    const int m0   = blockIdx.y * 128;
    const int n0   = blockIdx.x * 128;
    const int KT   = K >> 7;

    if (warp == 0) TCGEN05_ALLOC(sm0, 128);
    if (tid < STAGES) MBARRIER_INIT(mbar0 + tid * 8, 1);
    if (tid >= 64 && tid < 192) {
        int c = tid - 64;
        biasS[c] = (n0 + c < N) ? bias[n0 + c] : 0.f;
    }
    __syncthreads();

    uint32_t tmem;
    asm volatile("ld.shared.b32 %0, [%1];" : "=r"(tmem) : "r"(sm0));

    auto issue = [&](int kt, int buf) {
        const uint32_t aS = sA0 + buf * STG_BYTES;
        const uint32_t bS = aS + ABYTES;
        const int k0 = kt << 7;
#pragma unroll
        for (int i = 0; i < 8; i++) {
            int v = tid + i * 256;            // 0..2047
            int r = v >> 4;                   // row 0..127
            int c = v & 15;                   // 16B chunk within 256B row
            uint32_t off = ((uint32_t)(r >> 3) << 10) + ((uint32_t)(c >> 3) << 14)
                         + ((uint32_t)(r & 7) << 7) + ((uint32_t)(c & 7) << 4);
            off ^= (off >> 3) & 0x70u;
            cp16(aS + off, A + (size_t)(m0 + r) * lda + k0 + (c << 3));
            cp16(bS + off, W + (size_t)(n0 + r) * ldw + k0 + (c << 3));
        }
        cp_commit();
    };

    issue(0, 0); issue(1, 1); issue(2, 2);

    for (int kt = 0; kt < KT; kt++) {
        const int buf = kt % STAGES;
        const int rem = KT - kt - 1;
        if (rem >= 2)      cp_wait<2>();
        else if (rem == 1) cp_wait<1>();
        else               cp_wait<0>();
        FENCE_PROXY_ASYNC();          // cp.async (generic proxy) -> tcgen05 (async proxy)
        __syncthreads();

        if (warp == 0 && elect1()) {
            const uint32_t aS = sA0 + buf * STG_BYTES;
            const uint64_t ad = DESC_BASE | ((aS >> 4) & 0x3FFF);
            const uint64_t bd = DESC_BASE | (((aS + ABYTES) >> 4) & 0x3FFF);
#pragma unroll
            for (int j = 0; j < 8; j++) {
                uint64_t off = (j < 4) ? (uint64_t)(2 * j) : (uint64_t)(1024 + 2 * (j - 4));
                mma_bf16_ss(tmem, ad + off, bd + off, (kt > 0 || j > 0) ? 1u : 0u);
            }
            TCGEN05_COMMIT(mbar0 + buf * 8);
        }

        if (kt + STAGES < KT) {
            MBARRIER_WAIT_PARITY(mbar0 + buf * 8, (uint32_t)((kt / STAGES) & 1));
            issue(kt + STAGES, buf);
        }
    }

    {
        const int lb = (KT - 1) % STAGES;
        MBARRIER_WAIT_PARITY(mbar0 + lb * 8, (uint32_t)(((KT - 1) / STAGES) & 1));
    }
    TCGEN05_FENCE_AFTER();

    if (warp < 4) {
        const int gm = m0 + warp * 32 + lane;
#pragma unroll
        for (int ch = 0; ch < 4; ch++) {
            uint32_t r[32];
            TCGEN05_LD_32X32B_X32(r, tmem + ch * 32);
            TCGEN05_WAIT_LD();
            const int nb = n0 + ch * 32;
            if (outF) {
                float* po = outF + (size_t)gm * ldc;
#pragma unroll
                for (int c = 0; c < 32; c++) {
                    int gn = nb + c;
                    if (gn < N) {
                        float v = __uint_as_float(r[c]) + biasS[ch * 32 + c];
                        if (do_relu) v = fmaxf(v, 0.f);
                        po[gn] = v;
                    }
                }
            } else {
                __nv_bfloat16* po = (gm < split) ? out1 + (size_t)gm * ldc
                                                 : out2 + (size_t)(gm - split) * ldc;
#pragma unroll
                for (int p = 0; p < 16; p++) {
                    int gn = nb + 2 * p;
                    if (gn < N) {
                        float v0 = __uint_as_float(r[2 * p])     + biasS[ch * 32 + 2 * p];
                        float v1 = __uint_as_float(r[2 * p + 1]) + biasS[ch * 32 + 2 * p + 1];
                        if (do_relu) { v0 = fmaxf(v0, 0.f); v1 = fmaxf(v1, 0.f); }
                        uint32_t pk;
                        asm("cvt.rn.bf16x2.f32 %0, %1, %2;" : "=r"(pk) : "f"(v1), "f"(v0));
                        *reinterpret_cast<uint32_t*>(po + gn) = pk;
                    }
                }
            }
        }
        TCGEN05_FENCE_BEFORE();
    }
    __syncthreads();
    if (warp == 0) {
        TCGEN05_RELINQUISH();
        TCGEN05_DEALLOC(tmem, 128);
    }
#else
    // ======================= wmma fallback (plain sm_103) =======================
#define LDSB 72   // bf16 elems per smem row (64 + 8 pad)
    extern __shared__ char smraw[];
    __nv_bfloat16* Asm = reinterpret_cast<__nv_bfloat16*>(smraw);
    __nv_bfloat16* Bsm = Asm + 2 * 128 * LDSB;

    const int tid  = threadIdx.x;
    const int warp = tid >> 5;
    const int lane = tid & 31;
    const int wm   = warp >> 2;
    const int wn   = warp & 3;
    const int m0   = blockIdx.y * 128;
    const int n0   = blockIdx.x * 128;

    wmma::fragment<wmma::accumulator, 16, 16, 16, float> acc[4][2];
#pragma unroll
    for (int i = 0; i < 4; i++)
#pragma unroll
        for (int j = 0; j < 2; j++)
            wmma::fill_fragment(acc[i][j], 0.0f);

    const int KT = K >> 6;

    auto issue = [&](int kt) {
        const int k0 = kt << 6;
        __nv_bfloat16* a = Asm + (kt & 1) * 128 * LDSB;
        __nv_bfloat16* b = Bsm + (kt & 1) * 128 * LDSB;
#pragma unroll
        for (int t = 0; t < 4; t++) {
            int v = tid + t * 256;
            int r = v >> 3;
            int c = (v & 7) << 3;
            cp16(sptr(a + r * LDSB + c), A + (size_t)(m0 + r) * lda + k0 + c);
            cp16(sptr(b + r * LDSB + c), W + (size_t)(n0 + r) * ldw + k0 + c);
        }
        cp_commit();
    };

    issue(0);
    for (int kt = 0; kt < KT; kt++) {
        if (kt + 1 < KT) { issue(kt + 1); cp_wait<1>(); }
        else             { cp_wait<0>(); }
        __syncthreads();

        const __nv_bfloat16* a = Asm + (kt & 1) * 128 * LDSB;
        const __nv_bfloat16* b = Bsm + (kt & 1) * 128 * LDSB;
#pragma unroll
        for (int kk = 0; kk < 64; kk += 16) {
            wmma::fragment<wmma::matrix_a, 16, 16, 16, __nv_bfloat16, wmma::row_major> af[4];
            wmma::fragment<wmma::matrix_b, 16, 16, 16, __nv_bfloat16, wmma::col_major> bf[2];
#pragma unroll
            for (int i = 0; i < 4; i++)
                wmma::load_matrix_sync(af[i], a + (wm * 64 + i * 16) * LDSB + kk, LDSB);
#pragma unroll
            for (int j = 0; j < 2; j++)
                wmma::load_matrix_sync(bf[j], b + (wn * 32 + j * 16) * LDSB + kk, LDSB);
#pragma unroll
            for (int i = 0; i < 4; i++)
#pragma unroll
                for (int j = 0; j < 2; j++)
                    wmma::mma_sync(acc[i][j], af[i], bf[j], acc[i][j]);
        }
        __syncthreads();
    }

    float* st = reinterpret_cast<float*>(smraw) + warp * 256;
#pragma unroll
    for (int i = 0; i < 4; i++) {
#pragma unroll
        for (int j = 0; j < 2; j++) {
            wmma::store_matrix_sync(st, acc[i][j], 16, wmma::mem_row_major);
            __syncwarp();
            int m_base = m0 + wm * 64 + i * 16;
            int n_base = n0 + wn * 32 + j * 16;
#pragma unroll
            for (int e = 0; e < 8; e++) {
                int idx = lane * 8 + e;
                int r = idx >> 4, c = idx & 15;
                int gm = m_base + r;
                int gn = n_base + c;
                if (gn < N) {
                    float vv = st[idx] + bias[gn];
                    if (do_relu) vv = fmaxf(vv, 0.f);
                    if (outF) {
                        outF[(size_t)gm * ldc + gn] = vv;
                    } else {
                        __nv_bfloat16 hv = __float2bfloat16(vv);
                        if (gm < split) out1[(size_t)gm * ldc + gn] = hv;
                        else            out2[(size_t)(gm - split) * ldc + gn] = hv;
                    }
                }
            }
            __syncwarp();
        }
    }
#endif
}

// ---------------------------------------------------------------------------
// Scoring
// ---------------------------------------------------------------------------
__global__ void score_kernel(const float* __restrict__ L,
                             const int* __restrict__ pls,
                             const int* __restrict__ nls,
                             float* __restrict__ out) {
    int b = blockIdx.x;
    __shared__ float es[ED];
    for (int i = threadIdx.x; i < ED; i += blockDim.x) es[i] = g_emb[b * ED + i];
    __syncthreads();

    int warp = threadIdx.x >> 5;
    int lane = threadIdx.x & 31;
    for (int j = warp; j < NNEG + 1; j += 8) {
        int idx = (j == 0) ? pls[b] : nls[b * NNEG + (j - 1)];
        const float* Lr = L + (size_t)idx * ED;
        float s = 0.f;
        for (int c = lane; c < ED; c += 32) {
            float d = fmaxf(Lr[c] - es[c], 0.f);
            s += d * d;
        }
#pragma unroll
        for (int o = 16; o; o >>= 1) s += __shfl_xor_sync(0xffffffffu, s, o);
        if (lane == 0) out[b * (NNEG + 1) + j] = -sqrtf(s);
    }
}

// ---------------------------------------------------------------------------
// Launch
// ---------------------------------------------------------------------------
extern "C" void kernel_launch(void* const* d_in, const int* in_sizes, int n_in,
                              void* d_out, int out_size) {
    const float* vfs  = (const float*)d_in[0];
    const float* L    = (const float*)d_in[1];
    const int*   pls  = (const int*)  d_in[2];
    const int*   nls  = (const int*)  d_in[3];
    const float* W_h1 = (const float*)d_in[4];
    const float* b_h1 = (const float*)d_in[5];
    const float* W_e1 = (const float*)d_in[6];
    const float* b_e1 = (const float*)d_in[7];
    const float* W_h2 = (const float*)d_in[8];
    const float* b_h2 = (const float*)d_in[9];
    const float* W_e2 = (const float*)d_in[10];
    const float* b_e2 = (const float*)d_in[11];
    const float* W_h  = (const float*)d_in[12];
    const float* b_h  = (const float*)d_in[13];
    const float* W_e  = (const float*)d_in[14];
    const float* b_e  = (const float*)d_in[15];
    float* out = (float*)d_out;

    __nv_bfloat16 *pRv, *pX12, *pWh1, *pWe1, *pWh2, *pWe2, *pWh, *pWe;
    __nv_bfloat16 *pH1, *pH2, *pZ, *pH;
    float *pEmb;
    cudaGetSymbolAddress((void**)&pRv,  g_Rv);
    cudaGetSymbolAddress((void**)&pX12, g_X12);
    cudaGetSymbolAddress((void**)&pWh1, g_Wh1);
    cudaGetSymbolAddress((void**)&pWe1, g_We1);
    cudaGetSymbolAddress((void**)&pWh2, g_Wh2);
    cudaGetSymbolAddress((void**)&pWe2, g_We2);
    cudaGetSymbolAddress((void**)&pWh,  g_Wh);
    cudaGetSymbolAddress((void**)&pWe,  g_We);
    cudaGetSymbolAddress((void**)&pH1,  g_H1);
    cudaGetSymbolAddress((void**)&pH2,  g_H2);
    cudaGetSymbolAddress((void**)&pZ,   g_Z);
    cudaGetSymbolAddress((void**)&pH,   g_H);
    cudaGetSymbolAddress((void**)&pEmb, g_emb);

    cudaFuncSetAttribute(gemm_tc, cudaFuncAttributeMaxDynamicSharedMemorySize, GEMM_SMEM);

    const int T = 256;

    // zero padded regions
    cudaMemsetAsync(pWe1 + 600 * 2048, 0, (size_t)(NP600 - 600) * 2048 * 2);
    cudaMemsetAsync(pWe2 + 600 * 4096, 0, (size_t)(NP600 - 600) * 4096 * 2);
    cudaMemsetAsync(pWh,  0, (size_t)NP1800 * KP18 * 2);
    cudaMemsetAsync(pWe,  0, (size_t)NP600 * KP18 * 2);
    cudaMemsetAsync(pZ,   0, (size_t)1024 * KP18 * 2);
    cudaMemsetAsync(pH,   0, (size_t)1024 * KP18 * 2);

    auto cvt = [&](const float* s, __nv_bfloat16* d, int n, int relu_) {
        cvt_f32_b16<<<cdiv(n / 4, T), T>>>(s, d, n, relu_);
    };
    cvt(vfs,  pRv,  BATCH * VFS_D, 1);
    cvt(W_h1, pWh1, 2048 * 4096, 0);
    cvt(W_e1, pWe1, 600  * 2048, 0);
    cvt(W_h2, pWh2, 4096 * 12288, 0);
    cvt(W_e2, pWe2, 600  * 4096, 0);
    cvt2d_f32_b16<<<cdiv(1800 * 1800 / 4, T), T>>>(W_h, pWh, 1800, 1800, KP18);
    cvt2d_f32_b16<<<cdiv(600  * 1800 / 4, T), T>>>(W_e, pWe, 600,  1800, KP18);

    pack_x12<<<cdiv(2048 * 4096 / 8, T), T>>>();

    dim3 blk(256);
    // A: H1 = relu(X12 @ Wh1^T + b_h1)   [2048 x 2048], K=4096
    gemm_tc<<<dim3(16, 16), blk, GEMM_SMEM>>>(
        pX12, 4096, pWh1, 4096, b_h1, 2048, 4096,
        pH1, pH1, nullptr, 2048, 2048, 1);
    // C: H2 = relu(Rv @ Wh2^T + b_h2)    [1024 x 4096], K=12288
    gemm_tc<<<dim3(32, 8), blk, GEMM_SMEM>>>(
        pRv, VFS_D, pWh2, VFS_D, b_h2, 4096, VFS_D,
        pH2, pH2, nullptr, 4096, 1024, 1);
    // B: E1 -> Z[:,0:600] (rows<1024) / Z[:,1200:1800]
    gemm_tc<<<dim3(5, 16), blk, GEMM_SMEM>>>(
        pH1, 2048, pWe1, 2048, b_e1, 600, 2048,
        pZ, pZ + 1200, nullptr, KP18, 1024, 1);
    // D: E2 -> Z[:,600:1200]
    gemm_tc<<<dim3(5, 8), blk, GEMM_SMEM>>>(
        pH2, 4096, pWe2, 4096, b_e2, 600, 4096,
        pZ + 600, pZ + 600, nullptr, KP18, 1024, 1);
    // E: H = relu(Z @ Wh^T + b_h)        [1024 x 1800], K=1920
    gemm_tc<<<dim3(15, 8), blk, GEMM_SMEM>>>(
        pZ, KP18, pWh, KP18, b_h, 1800, KP18,
        pH, pH, nullptr, KP18, 1024, 1);
    // F: emb = H @ We^T + b_e            [1024 x 600] fp32
    gemm_tc<<<dim3(5, 8), blk, GEMM_SMEM>>>(
        pH, KP18, pWe, KP18, b_e, 600, KP18,
        nullptr, nullptr, pEmb, ED, 1024, 0);

    score_kernel<<<BATCH, 256>>>(L, pls, nls, out);
}